// round 14
// baseline (speedup 1.0000x reference)
#include <cuda_runtime.h>
#include <cuda_bf16.h>
#include <cuda_fp16.h>
#include <cstdint>
#include <math.h>

#define S_LEN 2048
#define B_SZ  4
#define M_ROWS (B_SZ*S_LEN)      // 8192
#define DIM_  2048
#define LAT_  512
#define KVD_  128
#define QKV_N 768                // 512 q | 128 k | 128 v
#define NH_   16
#define NKV_  4
#define HD_   32
#define EPS_  1e-6f
#define GAIN_ 0.25f
#define SQRT_HD 5.656854249492381f

// ---------------- scratch (device globals; no runtime allocation) ----------
__device__ uint32_t g_xh    [M_ROWS*(DIM_/2)];   // x packed fp16 hi pairs
__device__ uint32_t g_xl    [M_ROWS*(DIM_/2)];   // x packed fp16 lo pairs
__device__ uint32_t g_wqkvTh[(DIM_/2)*QKV_N];    // W^T qkv packed hi
__device__ uint32_t g_wqkvTl[(DIM_/2)*QKV_N];
__device__ uint32_t g_woTh  [(LAT_/2)*DIM_];     // W_o^T packed hi
__device__ uint32_t g_woTl  [(LAT_/2)*DIM_];
__device__ uint32_t g_ah    [M_ROWS*(LAT_/2)];   // rms(att) packed hi
__device__ uint32_t g_al    [M_ROWS*(LAT_/2)];
__device__ float g_qkv[M_ROWS*QKV_N];   // raw fused qkv gemm output
__device__ float g_qa  [M_ROWS*LAT_];   // q_pre (after rms g_latent)
__device__ float g_ka  [M_ROWS*KVD_];   // k_pre
__device__ float g_va  [M_ROWS*KVD_];   // v final
__device__ float g_qb  [M_ROWS*LAT_];   // conv out -> final q
__device__ float g_kb  [M_ROWS*KVD_];   // conv out -> final k
__device__ float g_att [M_ROWS*LAT_];   // attention output
__device__ float g_ropec[S_LEN*16];     // RoPE cos table (s, j)
__device__ float g_ropes[S_LEN*16];     // RoPE sin table (s, j)

__device__ __forceinline__ float warpSum(float v){
    #pragma unroll
    for (int o = 16; o; o >>= 1) v += __shfl_xor_sync(0xffffffffu, v, o);
    return v;
}

// split (a,b) into fp16 hi pair (returned) and lo pair (out param)
__device__ __forceinline__ uint32_t pack2(float a, float b, uint32_t& lo){
    __half ha = __float2half_rn(a), hb = __float2half_rn(b);
    __half la = __float2half_rn(a - __half2float(ha));
    __half lb = __float2half_rn(b - __half2float(hb));
    lo = (uint32_t)__half_as_ushort(la) | ((uint32_t)__half_as_ushort(lb) << 16);
    return (uint32_t)__half_as_ushort(ha) | ((uint32_t)__half_as_ushort(hb) << 16);
}

#define MMA_F16(c, a0,a1,a2,a3, b0,b1) \
  asm volatile("mma.sync.aligned.m16n8k16.row.col.f32.f16.f16.f32 " \
    "{%0,%1,%2,%3}, {%4,%5,%6,%7}, {%8,%9}, {%0,%1,%2,%3};" \
    : "+f"((c)[0]),"+f"((c)[1]),"+f"((c)[2]),"+f"((c)[3]) \
    : "r"(a0),"r"(a1),"r"(a2),"r"(a3),"r"(b0),"r"(b1))

// ---------------- RoPE table (one-time tiny kernel, fp64 off hot path) ------
__global__ void rope_table_kernel(){
    int s = blockIdx.x, j = threadIdx.x;            // j in [0,16)
    float freq = 1.0f / powf(10000.f, (float)(2*j) * (1.f/(float)HD_));
    float fang = (float)s * freq;                    // fp32 (matches jax)
    double sd_, cd_; sincos((double)fang, &sd_, &cd_);
    g_ropec[s*16 + j] = (float)cd_;
    g_ropes[s*16 + j] = (float)sd_;
}

// ---------------- pack x into hi/lo fp16 pair arrays ------------------------
__global__ void pack_x_kernel(const float* __restrict__ x){
    int idx = blockIdx.x * blockDim.x + threadIdx.x;
    if (idx >= M_ROWS * (DIM_/2)) return;
    float2 v = ((const float2*)x)[idx];
    uint32_t lo, hi = pack2(v.x, v.y, lo);
    g_xh[idx] = hi; g_xl[idx] = lo;
}

// ---------------- weight transpose+pack (sel: 0 wq, 1 wk, 2 wv, 3 wo) -------
__global__ void wpack_kernel(const float* __restrict__ w, int sel){
    int N, K2, ldOut, colOff; uint32_t *oh, *ol;
    if      (sel == 0){ N = LAT_; K2 = DIM_/2; ldOut = QKV_N; colOff = 0;   oh = g_wqkvTh; ol = g_wqkvTl; }
    else if (sel == 1){ N = KVD_; K2 = DIM_/2; ldOut = QKV_N; colOff = 512; oh = g_wqkvTh; ol = g_wqkvTl; }
    else if (sel == 2){ N = KVD_; K2 = DIM_/2; ldOut = QKV_N; colOff = 640; oh = g_wqkvTh; ol = g_wqkvTl; }
    else              { N = DIM_; K2 = LAT_/2; ldOut = DIM_;  colOff = 0;   oh = g_woTh;   ol = g_woTl;   }
    int idx = blockIdx.x * blockDim.x + threadIdx.x;
    if (idx >= N * K2) return;
    int n = idx / K2, p = idx - n * K2;
    float2 v = ((const float2*)w)[idx];
    uint32_t lo, hi = pack2(v.x, v.y, lo);
    oh[(size_t)p * ldOut + colOff + n] = hi;
    ol[(size_t)p * ldOut + colOff + n] = lo;
}

// ------------ 3x-split fp16 tensor-core GEMM: C[MxN] = A[MxK]*B[KxN] --------
#define GBM 128
#define GBN 128
#define SPAD 136
__global__ __launch_bounds__(512) void gemm_fp16x2_kernel(float* __restrict__ Cext, int sel)
{
    const uint32_t *Ah, *Al, *Bh, *Bl; float* C; int N, K2;
    if (sel == 0){ Ah = g_xh; Al = g_xl; Bh = g_wqkvTh; Bl = g_wqkvTl; C = g_qkv; N = QKV_N; K2 = DIM_/2; }
    else         { Ah = g_ah; Al = g_al; Bh = g_woTh;   Bl = g_woTl;   C = Cext;  N = DIM_;  K2 = LAT_/2; }

    __shared__ uint32_t AsH[2][8][SPAD], AsL[2][8][SPAD];
    __shared__ uint32_t BsH[2][8][SPAD], BsL[2][8][SPAD];

    const int tid  = threadIdx.x;
    const int warp = tid >> 5, lane = tid & 31;
    const int g = lane >> 2, tig = lane & 3;
    const int m0 = (warp >> 2) * 32;
    const int n0 = (warp & 3) * 32;

    const int aM = tid >> 2, aP = (tid & 3) * 2;
    const int bP = tid >> 6, bN = (tid & 63) * 2;

    const uint32_t* ApH = Ah + (size_t)(blockIdx.y * GBM + aM) * K2 + aP;
    const uint32_t* ApL = Al + (size_t)(blockIdx.y * GBM + aM) * K2 + aP;
    const uint32_t* BpH = Bh + (size_t)bP * N + blockIdx.x * GBN + bN;
    const uint32_t* BpL = Bl + (size_t)bP * N + blockIdx.x * GBN + bN;

    float acc[2][4][4];
    #pragma unroll
    for (int mt = 0; mt < 2; mt++)
        #pragma unroll
        for (int nt = 0; nt < 4; nt++)
            #pragma unroll
            for (int i = 0; i < 4; i++) acc[mt][nt][i] = 0.f;

    const int stages = K2 / 8;
    uint2 pah = *(const uint2*)ApH; uint2 pal = *(const uint2*)ApL;
    uint2 pbh = *(const uint2*)BpH; uint2 pbl = *(const uint2*)BpL;
    AsH[0][aP][aM] = pah.x; AsH[0][aP+1][aM] = pah.y;
    AsL[0][aP][aM] = pal.x; AsL[0][aP+1][aM] = pal.y;
    BsH[0][bP][bN] = pbh.x; BsH[0][bP][bN+1] = pbh.y;
    BsL[0][bP][bN] = pbl.x; BsL[0][bP][bN+1] = pbl.y;
    __syncthreads();

    for (int s = 0; s < stages; s++){
        const int cur = s & 1;
        if (s + 1 < stages){
            pah = *(const uint2*)(ApH + (s+1)*8);
            pal = *(const uint2*)(ApL + (s+1)*8);
            pbh = *(const uint2*)(BpH + (size_t)(s+1)*8 * N);
            pbl = *(const uint2*)(BpL + (size_t)(s+1)*8 * N);
        }
        uint32_t bh[4][2], bl[4][2];
        #pragma unroll
        for (int nt = 0; nt < 4; nt++){
            bh[nt][0] = BsH[cur][tig  ][n0 + nt*8 + g];
            bh[nt][1] = BsH[cur][tig+4][n0 + nt*8 + g];
            bl[nt][0] = BsL[cur][tig  ][n0 + nt*8 + g];
            bl[nt][1] = BsL[cur][tig+4][n0 + nt*8 + g];
        }
        #pragma unroll
        for (int mt = 0; mt < 2; mt++){
            uint32_t ah0 = AsH[cur][tig  ][m0 + mt*16 + g    ];
            uint32_t ah1 = AsH[cur][tig  ][m0 + mt*16 + g + 8];
            uint32_t ah2 = AsH[cur][tig+4][m0 + mt*16 + g    ];
            uint32_t ah3 = AsH[cur][tig+4][m0 + mt*16 + g + 8];
            uint32_t al0 = AsL[cur][tig  ][m0 + mt*16 + g    ];
            uint32_t al1 = AsL[cur][tig  ][m0 + mt*16 + g + 8];
            uint32_t al2 = AsL[cur][tig+4][m0 + mt*16 + g    ];
            uint32_t al3 = AsL[cur][tig+4][m0 + mt*16 + g + 8];
            #pragma unroll
            for (int nt = 0; nt < 4; nt++){
                MMA_F16(acc[mt][nt], ah0,ah1,ah2,ah3, bh[nt][0], bh[nt][1]);
                MMA_F16(acc[mt][nt], ah0,ah1,ah2,ah3, bl[nt][0], bl[nt][1]);
                MMA_F16(acc[mt][nt], al0,al1,al2,al3, bh[nt][0], bh[nt][1]);
            }
        }
        if (s + 1 < stages){
            const int nxt = cur ^ 1;
            AsH[nxt][aP][aM] = pah.x; AsH[nxt][aP+1][aM] = pah.y;
            AsL[nxt][aP][aM] = pal.x; AsL[nxt][aP+1][aM] = pal.y;
            BsH[nxt][bP][bN] = pbh.x; BsH[nxt][bP][bN+1] = pbh.y;
            BsL[nxt][bP][bN] = pbl.x; BsL[nxt][bP][bN+1] = pbl.y;
        }
        __syncthreads();
    }

    const int rowBase = blockIdx.y * GBM + m0 + g;
    const int colBase = blockIdx.x * GBN + n0;
    #pragma unroll
    for (int mt = 0; mt < 2; mt++){
        #pragma unroll
        for (int nt = 0; nt < 4; nt++){
            int row = rowBase + mt*16;
            int col = colBase + nt*8 + tig*2;
            *(float2*)&C[(size_t)row * N + col]       = make_float2(acc[mt][nt][0], acc[mt][nt][1]);
            *(float2*)&C[(size_t)(row + 8) * N + col] = make_float2(acc[mt][nt][2], acc[mt][nt][3]);
        }
    }
}

// ---------------- fused RMS over packed qkv output ---------------------------
__global__ __launch_bounds__(256) void rms_qkv_kernel(
    const float* __restrict__ gl, const float* __restrict__ gkv)
{
    const int row = blockIdx.x, t = threadIdx.x;
    const float* ip = g_qkv + (size_t)row * QKV_N;
    float q0 = ip[t], q1 = ip[t+256], kv = ip[512+t];
    bool isk = t < 128;
    float ssq = q0*q0 + q1*q1;
    float skv = kv*kv;
    float sk = isk ? skv : 0.f, sv = isk ? 0.f : skv;
    ssq = warpSum(ssq); sk = warpSum(sk); sv = warpSum(sv);
    __shared__ float rq[8], rk[8], rv[8];
    int lane = t & 31, wid = t >> 5;
    if (lane == 0){ rq[wid] = ssq; rk[wid] = sk; rv[wid] = sv; }
    __syncthreads();
    float tq = 0.f, tk = 0.f, tv = 0.f;
    #pragma unroll
    for (int i = 0; i < 8; i++){ tq += rq[i]; tk += rk[i]; tv += rv[i]; }
    float r_q = rsqrtf(tq * (1.f/512.f) + EPS_);
    float r_k = rsqrtf(tk * (1.f/128.f) + EPS_);
    float r_v = rsqrtf(tv * (1.f/128.f) + EPS_);
    g_qa[(size_t)row*LAT_ + t]       = q0 * r_q * gl[t];
    g_qa[(size_t)row*LAT_ + t + 256] = q1 * r_q * gl[t+256];
    float res = kv * (isk ? r_k : r_v) * gkv[t & 127];
    if (isk) g_ka[(size_t)row*KVD_ + t]         = res;
    else     g_va[(size_t)row*KVD_ + (t - 128)] = res;
}

// ---------------- pre-out RMS -> packed hi/lo for final GEMM -----------------
__global__ __launch_bounds__(128) void rms_att_pack_kernel(const float* __restrict__ g)
{
    const int row = blockIdx.x, t = threadIdx.x;
    const float* ip = g_att + (size_t)row * LAT_;
    float4 v = *(const float4*)(ip + 4*t);
    float ss = v.x*v.x + v.y*v.y + v.z*v.z + v.w*v.w;
    ss = warpSum(ss);
    __shared__ float red[4];
    int lane = t & 31, wid = t >> 5;
    if (lane == 0) red[wid] = ss;
    __syncthreads();
    float r = rsqrtf((red[0]+red[1]+red[2]+red[3]) * (1.f/512.f) + EPS_);
    float4 gg = *(const float4*)(g + 4*t);
    float a0 = v.x*r*gg.x, a1 = v.y*r*gg.y, a2 = v.z*r*gg.z, a3 = v.w*r*gg.w;
    uint32_t lo0, lo1;
    uint32_t hi0 = pack2(a0, a1, lo0);
    uint32_t hi1 = pack2(a2, a3, lo1);
    size_t base = (size_t)row * (LAT_/2) + 2*t;
    g_ah[base] = hi0; g_ah[base+1] = hi1;
    g_al[base] = lo0; g_al[base+1] = lo1;
}

// ---------------- grouped causal conv (q: 512 ch, 16 groups) + RMS ----------
__global__ __launch_bounds__(256) void convq_kernel(
    const float* __restrict__ w, const float* __restrict__ g)
{
    const float* qin = g_qa; float* out = g_qb;
    const int row = blockIdx.x;
    const int s = row & (S_LEN - 1);
    __shared__ __align__(16) float xin[3][LAT_];
    __shared__ float red[8];
    const int t = threadIdx.x;
    #pragma unroll
    for (int tt = 0; tt < 3; tt++){
        int sr = s - 2 + tt;
        for (int i = t; i < LAT_; i += 256)
            xin[tt][i] = (sr >= 0) ? qin[(size_t)(row - 2 + tt) * LAT_ + i] : 0.f;
    }
    __syncthreads();
    float acc[2]; float ss = 0.f;
    #pragma unroll
    for (int cc = 0; cc < 2; cc++){
        int c = t + cc * 256;
        int grp = c >> 5;
        const float* wc = w + c * 96;
        const float* x0 = &xin[0][grp*32];
        const float* x1 = &xin[1][grp*32];
        const float* x2 = &xin[2][grp*32];
        float a = 0.f;
        #pragma unroll
        for (int i = 0; i < 32; i++)
            a += wc[i*3]*x0[i] + wc[i*3+1]*x1[i] + wc[i*3+2]*x2[i];
        acc[cc] = a; ss += a*a;
    }
    ss = warpSum(ss);
    int lane = t & 31, wid = t >> 5;
    if (lane == 0) red[wid] = ss;
    __syncthreads();
    float tot = 0.f;
    #pragma unroll
    for (int i = 0; i < 8; i++) tot += red[i];
    float r = rsqrtf(tot * (1.f/(float)LAT_) + EPS_);
    out[(size_t)row*LAT_ + t]       = acc[0] * r * g[t];
    out[(size_t)row*LAT_ + t + 256] = acc[1] * r * g[t+256];
}

// ---------------- grouped causal conv (k: 128 ch, 4 groups) + RMS -----------
__global__ __launch_bounds__(128) void convk_kernel(
    const float* __restrict__ w, const float* __restrict__ g)
{
    const float* kin = g_ka; float* out = g_kb;
    const int row = blockIdx.x;
    const int s = row & (S_LEN - 1);
    __shared__ __align__(16) float xin[3][KVD_];
    __shared__ float red[4];
    const int t = threadIdx.x;
    #pragma unroll
    for (int tt = 0; tt < 3; tt++){
        int sr = s - 2 + tt;
        xin[tt][t] = (sr >= 0) ? kin[(size_t)(row - 2 + tt) * KVD_ + t] : 0.f;
    }
    __syncthreads();
    int grp = t >> 5;
    const float* wc = w + t * 96;
    float a = 0.f;
    #pragma unroll
    for (int i = 0; i < 32; i++)
        a += wc[i*3]*xin[0][grp*32+i] + wc[i*3+1]*xin[1][grp*32+i] + wc[i*3+2]*xin[2][grp*32+i];
    float ss = warpSum(a*a);
    int lane = t & 31, wid = t >> 5;
    if (lane == 0) red[wid] = ss;
    __syncthreads();
    float r = rsqrtf((red[0]+red[1]+red[2]+red[3]) * (1.f/(float)KVD_) + EPS_);
    out[(size_t)row*KVD_ + t] = a * r * g[t];
}

// ---------------- post: means coupling, post-RMS, per-head norm, RoPE -------
__global__ __launch_bounds__(512) void post_kernel(
    const float* __restrict__ g_postq, const float* __restrict__ g_postk,
    const float* __restrict__ key_temp)
{
    const float* qpre = g_qa; const float* kpre = g_ka;
    float* qio = g_qb; float* kio = g_kb;
    const int row = blockIdx.x;
    const int s = row & (S_LEN - 1);
    const int t = threadIdx.x;
    const int lane = t & 31, wid = t >> 5;
    __shared__ float shq[LAT_];
    __shared__ float kmean[HD_], qmean[HD_];
    __shared__ float red[16];

    shq[t] = qpre[(size_t)row*LAT_ + t];
    __syncthreads();
    if (t < 32){
        float qm = 0.f;
        #pragma unroll
        for (int h = 0; h < NH_; h++) qm += shq[h*32 + t];
        qmean[t] = qm * (1.f/(float)NH_);
        float km = 0.f;
        #pragma unroll
        for (int kh = 0; kh < NKV_; kh++) km += kpre[(size_t)row*KVD_ + kh*32 + t];
        kmean[t] = km * (1.f/(float)NKV_);
    }
    __syncthreads();

    // RoPE from precomputed table
    const int j = lane >> 1;
    const float c  = g_ropec[s*16 + j];
    const float si = g_ropes[s*16 + j];

    // ---- Q path ----
    float qv = qio[(size_t)row*LAT_ + t] + GAIN_ * kmean[lane];
    float ss = warpSum(qv*qv);
    if (lane == 0) red[wid] = ss;
    __syncthreads();
    float tot = 0.f;
    #pragma unroll
    for (int i = 0; i < 16; i++) tot += red[i];
    float r = rsqrtf(tot * (1.f/(float)LAT_) + EPS_);
    qv = qv * r * g_postq[t];
    float n2 = warpSum(qv*qv);
    float nrm = fmaxf(sqrtf(n2), 1e-12f);
    qv = qv * (SQRT_HD / nrm);
    {
        float other = __shfl_xor_sync(0xffffffffu, qv, 1);
        float res = (lane & 1) ? fmaf(other, si, qv * c)
                               : fmaf(qv, c, -other * si);
        qio[(size_t)row*LAT_ + t] = res;
    }

    // ---- K path ----
    float kvv = (t < KVD_) ? (kio[(size_t)row*KVD_ + t] + GAIN_ * qmean[lane]) : 0.f;
    __syncthreads();
    float ssk = warpSum(kvv*kvv);
    if (lane == 0) red[wid] = ssk;
    __syncthreads();
    float totk = 0.f;
    #pragma unroll
    for (int i = 0; i < 16; i++) totk += red[i];
    if (t < KVD_){
        float rk = rsqrtf(totk * (1.f/(float)KVD_) + EPS_);
        kvv = kvv * rk * g_postk[t];
        float n2k = warpSum(kvv*kvv);
        float nk = fmaxf(sqrtf(n2k), 1e-12f);
        kvv = kvv * (SQRT_HD / nk) * key_temp[0];
        float other = __shfl_xor_sync(0xffffffffu, kvv, 1);
        float res = (lane & 1) ? fmaf(other, si, kvv * c)
                               : fmaf(kvv, c, -other * si);
        kio[(size_t)row*KVD_ + t] = res;
    }
}

// ------ flash attention, UNNORMALIZED softmax (bounded logits, no max) ------
// |logit| <= sqrt(32)*key_temp*~1 => exp safe in fp32; sum <= ~6e5.
__global__ __launch_bounds__(256) void flash_kernel()
{
    const float* Q = g_qb; const float* Kk = g_kb;
    const float* V = g_va; float* O = g_att;
    const int qt = blockIdx.x, h = blockIdx.y, b = blockIdx.z;
    const int kh = h >> 2;
    const int tid = threadIdx.x;
    const int tx = tid & 15, ty = tid >> 4;
    __shared__ __align__(16) float qs[64][36];
    __shared__ __align__(16) float ks[64][36];
    __shared__ __align__(16) float vs[64][36];
    __shared__ __align__(16) float ps[64][68];
    const int q0 = qt * 64;

    for (int idx = tid; idx < 512; idx += 256){
        int r = idx >> 3, cv = (idx & 7) * 4;
        *(float4*)&qs[r][cv] =
            *(const float4*)&Q[((size_t)(b*S_LEN + q0 + r))*LAT_ + h*HD_ + cv];
    }
    float l[4], o0[4], o1[4];
    #pragma unroll
    for (int r = 0; r < 4; r++){ l[r] = 0.f; o0[r] = 0.f; o1[r] = 0.f; }
    const float scale = 0.1767766952966369f; // 1/sqrt(32)
    const int d0 = tx * 2;

    for (int kt = 0; kt <= qt; kt++){
        const int k0 = kt * 64;
        __syncthreads();
        for (int idx = tid; idx < 512; idx += 256){
            int r = idx >> 3, cv = (idx & 7) * 4;
            size_t base = ((size_t)(b*S_LEN + k0 + r))*KVD_ + kh*HD_ + cv;
            *(float4*)&ks[r][cv] = *(const float4*)&Kk[base];
            *(float4*)&vs[r][cv] = *(const float4*)&V[base];
        }
        __syncthreads();

        float sc[4][4];
        #pragma unroll
        for (int r = 0; r < 4; r++)
            #pragma unroll
            for (int c = 0; c < 4; c++) sc[r][c] = 0.f;
        #pragma unroll
        for (int d = 0; d < 32; d += 4){
            float4 qa4[4], kb4[4];
            #pragma unroll
            for (int r = 0; r < 4; r++) qa4[r] = *(const float4*)&qs[ty*4+r][d];
            #pragma unroll
            for (int c = 0; c < 4; c++) kb4[c] = *(const float4*)&ks[tx*4+c][d];
            #pragma unroll
            for (int r = 0; r < 4; r++)
                #pragma unroll
                for (int c = 0; c < 4; c++){
                    sc[r][c] = fmaf(qa4[r].x, kb4[c].x, sc[r][c]);
                    sc[r][c] = fmaf(qa4[r].y, kb4[c].y, sc[r][c]);
                    sc[r][c] = fmaf(qa4[r].z, kb4[c].z, sc[r][c]);
                    sc[r][c] = fmaf(qa4[r].w, kb4[c].w, sc[r][c]);
                }
        }
        // exp (with causal mask on diagonal tile), accumulate partial row sums
        if (kt == qt){
            #pragma unroll
            for (int r = 0; r < 4; r++)
                #pragma unroll
                for (int c = 0; c < 4; c++){
                    bool ok = (k0 + tx*4 + c <= q0 + ty*4 + r);
                    float p = ok ? __expf(sc[r][c]*scale) : 0.f;
                    ps[ty*4+r][tx*4+c] = p;
                    l[r] += p;
                }
        } else {
            #pragma unroll
            for (int r = 0; r < 4; r++)
                #pragma unroll
                for (int c = 0; c < 4; c++){
                    float p = __expf(sc[r][c]*scale);
                    ps[ty*4+r][tx*4+c] = p;
                    l[r] += p;
                }
        }
        __syncthreads();
        #pragma unroll 4
        for (int n = 0; n < 64; n += 4){
            float4 p4[4];
            #pragma unroll
            for (int r = 0; r < 4; r++) p4[r] = *(const float4*)&ps[ty*4+r][n];
            #pragma unroll
            for (int jj = 0; jj < 4; jj++){
                float v0 = vs[n+jj][d0], v1 = vs[n+jj][d0+1];
                float p0 = (jj==0)?p4[0].x:(jj==1)?p4[0].y:(jj==2)?p4[0].z:p4[0].w;
                float p1 = (jj==0)?p4[1].x:(jj==1)?p4[1].y:(jj==2)?p4[1].z:p4[1].w;
                float p2 = (jj==0)?p4[2].x:(jj==1)?p4[2].y:(jj==2)?p4[2].z:p4[2].w;
                float p3 = (jj==0)?p4[3].x:(jj==1)?p4[3].y:(jj==2)?p4[3].z:p4[3].w;
                o0[0] = fmaf(p0, v0, o0[0]); o1[0] = fmaf(p0, v1, o1[0]);
                o0[1] = fmaf(p1, v0, o0[1]); o1[1] = fmaf(p1, v1, o1[1]);
                o0[2] = fmaf(p2, v0, o0[2]); o1[2] = fmaf(p2, v1, o1[2]);
                o0[3] = fmaf(p3, v0, o0[3]); o1[3] = fmaf(p3, v1, o1[3]);
            }
        }
    }
    // one final reduction of row sums across the 16 tx threads
    #pragma unroll
    for (int r = 0; r < 4; r++){
        float lr = l[r];
        #pragma unroll
        for (int off = 8; off; off >>= 1)
            lr += __shfl_xor_sync(0xffffffffu, lr, off, 16);
        float inv = 1.f / lr;
        size_t base = ((size_t)(b*S_LEN + q0 + ty*4 + r))*LAT_ + h*HD_ + d0;
        O[base]   = o0[r] * inv;
        O[base+1] = o1[r] * inv;
    }
}

// ---------------- host launcher ---------------------------------------------
extern "C" void kernel_launch(void* const* d_in, const int* in_sizes, int n_in,
                              void* d_out, int out_size)
{
    const float *x, *w_q, *w_k, *w_v, *g_latent, *g_kv, *conv_q_w, *conv_k_w;
    const float *g_conv, *g_kconv, *g_postq, *g_postk, *key_temp, *g_preout, *w_o;

    if (n_in >= 15 && in_sizes[0] == M_ROWS * DIM_) {
        x        = (const float*)d_in[0];
        w_q      = (const float*)d_in[1];
        w_k      = (const float*)d_in[2];
        w_v      = (const float*)d_in[3];
        g_latent = (const float*)d_in[4];
        g_kv     = (const float*)d_in[5];
        conv_q_w = (const float*)d_in[6];
        conv_k_w = (const float*)d_in[7];
        g_conv   = (const float*)d_in[8];
        g_kconv  = (const float*)d_in[9];
        g_postq  = (const float*)d_in[10];
        g_postk  = (const float*)d_in[11];
        key_temp = (const float*)d_in[12];
        g_preout = (const float*)d_in[13];
        w_o      = (const float*)d_in[14];
    } else {
        conv_k_w = (const float*)d_in[0];
        conv_q_w = (const float*)d_in[1];
        g_conv   = (const float*)d_in[2];
        g_kconv  = (const float*)d_in[3];
        g_kv     = (const float*)d_in[4];
        g_latent = (const float*)d_in[5];
        g_postk  = (const float*)d_in[6];
        g_postq  = (const float*)d_in[7];
        g_preout = (const float*)d_in[8];
        key_temp = (const float*)d_in[9];
        w_k      = (const float*)d_in[10];
        w_o      = (const float*)d_in[11];
        w_q      = (const float*)d_in[12];
        w_v      = (const float*)d_in[13];
        x        = (const float*)d_in[14];
    }
    float* out = (float*)d_out;

    rope_table_kernel<<<S_LEN, 16>>>();
    pack_x_kernel<<<(M_ROWS*(DIM_/2)+255)/256, 256>>>(x);
    wpack_kernel<<<(LAT_*(DIM_/2)+255)/256, 256>>>(w_q, 0);
    wpack_kernel<<<(KVD_*(DIM_/2)+255)/256, 256>>>(w_k, 1);
    wpack_kernel<<<(KVD_*(DIM_/2)+255)/256, 256>>>(w_v, 2);
    wpack_kernel<<<(DIM_*(LAT_/2)+255)/256, 256>>>(w_o, 3);

    gemm_fp16x2_kernel<<<dim3(QKV_N/GBN, M_ROWS/GBM), 512>>>(nullptr, 0);

    rms_qkv_kernel<<<M_ROWS, 256>>>(g_latent, g_kv);

    convq_kernel<<<M_ROWS, 256>>>(conv_q_w, g_conv);
    convk_kernel<<<M_ROWS, 128>>>(conv_k_w, g_kconv);

    post_kernel<<<M_ROWS, 512>>>(g_postq, g_postk, key_temp);

    flash_kernel<<<dim3(S_LEN/64, NH_, B_SZ), 256>>>();

    rms_att_pack_kernel<<<M_ROWS, 128>>>(g_preout);

    gemm_fp16x2_kernel<<<dim3(DIM_/GBN, M_ROWS/GBM), 512>>>(out, 1);
}

// round 15
// speedup vs baseline: 1.0006x; 1.0006x over previous
#include <cuda_runtime.h>
#include <cuda_bf16.h>
#include <cuda_fp16.h>
#include <cstdint>
#include <math.h>

#define S_LEN 2048
#define B_SZ  4
#define M_ROWS (B_SZ*S_LEN)      // 8192
#define DIM_  2048
#define LAT_  512
#define KVD_  128
#define QKV_N 768                // 512 q | 128 k | 128 v
#define NH_   16
#define NKV_  4
#define HD_   32
#define EPS_  1e-6f
#define GAIN_ 0.25f
#define SQRT_HD 5.656854249492381f

// ---------------- scratch (device globals; no runtime allocation) ----------
__device__ uint32_t g_xh    [M_ROWS*(DIM_/2)];   // x packed fp16 hi pairs
__device__ uint32_t g_xl    [M_ROWS*(DIM_/2)];   // x packed fp16 lo pairs
__device__ uint32_t g_wqkvTh[(DIM_/2)*QKV_N];    // W^T qkv packed hi
__device__ uint32_t g_wqkvTl[(DIM_/2)*QKV_N];
__device__ uint32_t g_woTh  [(LAT_/2)*DIM_];     // W_o^T packed hi
__device__ uint32_t g_woTl  [(LAT_/2)*DIM_];
__device__ uint32_t g_ah    [M_ROWS*(LAT_/2)];   // rms(att) packed hi
__device__ uint32_t g_al    [M_ROWS*(LAT_/2)];
__device__ float g_qkv[M_ROWS*QKV_N];   // raw fused qkv gemm output
__device__ float g_qa  [M_ROWS*LAT_];   // q_pre (after rms g_latent)
__device__ float g_ka  [M_ROWS*KVD_];   // k_pre
__device__ float g_va  [M_ROWS*KVD_];   // v final
__device__ float g_qb  [M_ROWS*LAT_];   // conv out -> final q
__device__ float g_kb  [M_ROWS*KVD_];   // conv out -> final k
__device__ float g_att [M_ROWS*LAT_];   // attention output
__device__ float g_ropec[S_LEN*16];     // RoPE cos table (s, j)
__device__ float g_ropes[S_LEN*16];     // RoPE sin table (s, j)

__device__ __forceinline__ float warpSum(float v){
    #pragma unroll
    for (int o = 16; o; o >>= 1) v += __shfl_xor_sync(0xffffffffu, v, o);
    return v;
}

// split (a,b) into fp16 hi pair (returned) and lo pair (out param)
__device__ __forceinline__ uint32_t pack2(float a, float b, uint32_t& lo){
    __half ha = __float2half_rn(a), hb = __float2half_rn(b);
    __half la = __float2half_rn(a - __half2float(ha));
    __half lb = __float2half_rn(b - __half2float(hb));
    lo = (uint32_t)__half_as_ushort(la) | ((uint32_t)__half_as_ushort(lb) << 16);
    return (uint32_t)__half_as_ushort(ha) | ((uint32_t)__half_as_ushort(hb) << 16);
}

#define MMA_F16(c, a0,a1,a2,a3, b0,b1) \
  asm volatile("mma.sync.aligned.m16n8k16.row.col.f32.f16.f16.f32 " \
    "{%0,%1,%2,%3}, {%4,%5,%6,%7}, {%8,%9}, {%0,%1,%2,%3};" \
    : "+f"((c)[0]),"+f"((c)[1]),"+f"((c)[2]),"+f"((c)[3]) \
    : "r"(a0),"r"(a1),"r"(a2),"r"(a3),"r"(b0),"r"(b1))

// ---------------- RoPE table (one-time tiny kernel, fp64 off hot path) ------
__global__ void rope_table_kernel(){
    int s = blockIdx.x, j = threadIdx.x;            // j in [0,16)
    float freq = 1.0f / powf(10000.f, (float)(2*j) * (1.f/(float)HD_));
    float fang = (float)s * freq;                    // fp32 (matches jax)
    double sd_, cd_; sincos((double)fang, &sd_, &cd_);
    g_ropec[s*16 + j] = (float)cd_;
    g_ropes[s*16 + j] = (float)sd_;
}

// ---------------- pack x into hi/lo fp16 pair arrays ------------------------
__global__ void pack_x_kernel(const float* __restrict__ x){
    int idx = blockIdx.x * blockDim.x + threadIdx.x;
    if (idx >= M_ROWS * (DIM_/2)) return;
    float2 v = ((const float2*)x)[idx];
    uint32_t lo, hi = pack2(v.x, v.y, lo);
    g_xh[idx] = hi; g_xl[idx] = lo;
}

// ---------------- weight transpose+pack (sel: 0 wq, 1 wk, 2 wv, 3 wo) -------
__global__ void wpack_kernel(const float* __restrict__ w, int sel){
    int N, K2, ldOut, colOff; uint32_t *oh, *ol;
    if      (sel == 0){ N = LAT_; K2 = DIM_/2; ldOut = QKV_N; colOff = 0;   oh = g_wqkvTh; ol = g_wqkvTl; }
    else if (sel == 1){ N = KVD_; K2 = DIM_/2; ldOut = QKV_N; colOff = 512; oh = g_wqkvTh; ol = g_wqkvTl; }
    else if (sel == 2){ N = KVD_; K2 = DIM_/2; ldOut = QKV_N; colOff = 640; oh = g_wqkvTh; ol = g_wqkvTl; }
    else              { N = DIM_; K2 = LAT_/2; ldOut = DIM_;  colOff = 0;   oh = g_woTh;   ol = g_woTl;   }
    int idx = blockIdx.x * blockDim.x + threadIdx.x;
    if (idx >= N * K2) return;
    int n = idx / K2, p = idx - n * K2;
    float2 v = ((const float2*)w)[idx];
    uint32_t lo, hi = pack2(v.x, v.y, lo);
    oh[(size_t)p * ldOut + colOff + n] = hi;
    ol[(size_t)p * ldOut + colOff + n] = lo;
}

// ------------ 3x-split fp16 tensor-core GEMM: C[MxN] = A[MxK]*B[KxN] --------
#define GBM 128
#define GBN 128
#define SPAD 136
__global__ __launch_bounds__(512) void gemm_fp16x2_kernel(float* __restrict__ Cext, int sel)
{
    const uint32_t *Ah, *Al, *Bh, *Bl; float* C; int N, K2;
    if (sel == 0){ Ah = g_xh; Al = g_xl; Bh = g_wqkvTh; Bl = g_wqkvTl; C = g_qkv; N = QKV_N; K2 = DIM_/2; }
    else         { Ah = g_ah; Al = g_al; Bh = g_woTh;   Bl = g_woTl;   C = Cext;  N = DIM_;  K2 = LAT_/2; }

    __shared__ uint32_t AsH[2][8][SPAD], AsL[2][8][SPAD];
    __shared__ uint32_t BsH[2][8][SPAD], BsL[2][8][SPAD];

    const int tid  = threadIdx.x;
    const int warp = tid >> 5, lane = tid & 31;
    const int g = lane >> 2, tig = lane & 3;
    const int m0 = (warp >> 2) * 32;
    const int n0 = (warp & 3) * 32;

    const int aM = tid >> 2, aP = (tid & 3) * 2;
    const int bP = tid >> 6, bN = (tid & 63) * 2;

    const uint32_t* ApH = Ah + (size_t)(blockIdx.y * GBM + aM) * K2 + aP;
    const uint32_t* ApL = Al + (size_t)(blockIdx.y * GBM + aM) * K2 + aP;
    const uint32_t* BpH = Bh + (size_t)bP * N + blockIdx.x * GBN + bN;
    const uint32_t* BpL = Bl + (size_t)bP * N + blockIdx.x * GBN + bN;

    float acc[2][4][4];
    #pragma unroll
    for (int mt = 0; mt < 2; mt++)
        #pragma unroll
        for (int nt = 0; nt < 4; nt++)
            #pragma unroll
            for (int i = 0; i < 4; i++) acc[mt][nt][i] = 0.f;

    const int stages = K2 / 8;
    uint2 pah = *(const uint2*)ApH; uint2 pal = *(const uint2*)ApL;
    uint2 pbh = *(const uint2*)BpH; uint2 pbl = *(const uint2*)BpL;
    AsH[0][aP][aM] = pah.x; AsH[0][aP+1][aM] = pah.y;
    AsL[0][aP][aM] = pal.x; AsL[0][aP+1][aM] = pal.y;
    BsH[0][bP][bN] = pbh.x; BsH[0][bP][bN+1] = pbh.y;
    BsL[0][bP][bN] = pbl.x; BsL[0][bP][bN+1] = pbl.y;
    __syncthreads();

    for (int s = 0; s < stages; s++){
        const int cur = s & 1;
        if (s + 1 < stages){
            pah = *(const uint2*)(ApH + (s+1)*8);
            pal = *(const uint2*)(ApL + (s+1)*8);
            pbh = *(const uint2*)(BpH + (size_t)(s+1)*8 * N);
            pbl = *(const uint2*)(BpL + (size_t)(s+1)*8 * N);
        }
        uint32_t bh[4][2], bl[4][2];
        #pragma unroll
        for (int nt = 0; nt < 4; nt++){
            bh[nt][0] = BsH[cur][tig  ][n0 + nt*8 + g];
            bh[nt][1] = BsH[cur][tig+4][n0 + nt*8 + g];
            bl[nt][0] = BsL[cur][tig  ][n0 + nt*8 + g];
            bl[nt][1] = BsL[cur][tig+4][n0 + nt*8 + g];
        }
        #pragma unroll
        for (int mt = 0; mt < 2; mt++){
            uint32_t ah0 = AsH[cur][tig  ][m0 + mt*16 + g    ];
            uint32_t ah1 = AsH[cur][tig  ][m0 + mt*16 + g + 8];
            uint32_t ah2 = AsH[cur][tig+4][m0 + mt*16 + g    ];
            uint32_t ah3 = AsH[cur][tig+4][m0 + mt*16 + g + 8];
            uint32_t al0 = AsL[cur][tig  ][m0 + mt*16 + g    ];
            uint32_t al1 = AsL[cur][tig  ][m0 + mt*16 + g + 8];
            uint32_t al2 = AsL[cur][tig+4][m0 + mt*16 + g    ];
            uint32_t al3 = AsL[cur][tig+4][m0 + mt*16 + g + 8];
            #pragma unroll
            for (int nt = 0; nt < 4; nt++){
                MMA_F16(acc[mt][nt], ah0,ah1,ah2,ah3, bh[nt][0], bh[nt][1]);
                MMA_F16(acc[mt][nt], ah0,ah1,ah2,ah3, bl[nt][0], bl[nt][1]);
                MMA_F16(acc[mt][nt], al0,al1,al2,al3, bh[nt][0], bh[nt][1]);
            }
        }
        if (s + 1 < stages){
            const int nxt = cur ^ 1;
            AsH[nxt][aP][aM] = pah.x; AsH[nxt][aP+1][aM] = pah.y;
            AsL[nxt][aP][aM] = pal.x; AsL[nxt][aP+1][aM] = pal.y;
            BsH[nxt][bP][bN] = pbh.x; BsH[nxt][bP][bN+1] = pbh.y;
            BsL[nxt][bP][bN] = pbl.x; BsL[nxt][bP][bN+1] = pbl.y;
        }
        __syncthreads();
    }

    const int rowBase = blockIdx.y * GBM + m0 + g;
    const int colBase = blockIdx.x * GBN + n0;
    #pragma unroll
    for (int mt = 0; mt < 2; mt++){
        #pragma unroll
        for (int nt = 0; nt < 4; nt++){
            int row = rowBase + mt*16;
            int col = colBase + nt*8 + tig*2;
            *(float2*)&C[(size_t)row * N + col]       = make_float2(acc[mt][nt][0], acc[mt][nt][1]);
            *(float2*)&C[(size_t)(row + 8) * N + col] = make_float2(acc[mt][nt][2], acc[mt][nt][3]);
        }
    }
}

// ---------------- fused RMS over packed qkv output ---------------------------
__global__ __launch_bounds__(256) void rms_qkv_kernel(
    const float* __restrict__ gl, const float* __restrict__ gkv)
{
    const int row = blockIdx.x, t = threadIdx.x;
    const float* ip = g_qkv + (size_t)row * QKV_N;
    float q0 = ip[t], q1 = ip[t+256], kv = ip[512+t];
    bool isk = t < 128;
    float ssq = q0*q0 + q1*q1;
    float skv = kv*kv;
    float sk = isk ? skv : 0.f, sv = isk ? 0.f : skv;
    ssq = warpSum(ssq); sk = warpSum(sk); sv = warpSum(sv);
    __shared__ float rq[8], rk[8], rv[8];
    int lane = t & 31, wid = t >> 5;
    if (lane == 0){ rq[wid] = ssq; rk[wid] = sk; rv[wid] = sv; }
    __syncthreads();
    float tq = 0.f, tk = 0.f, tv = 0.f;
    #pragma unroll
    for (int i = 0; i < 8; i++){ tq += rq[i]; tk += rk[i]; tv += rv[i]; }
    float r_q = rsqrtf(tq * (1.f/512.f) + EPS_);
    float r_k = rsqrtf(tk * (1.f/128.f) + EPS_);
    float r_v = rsqrtf(tv * (1.f/128.f) + EPS_);
    g_qa[(size_t)row*LAT_ + t]       = q0 * r_q * gl[t];
    g_qa[(size_t)row*LAT_ + t + 256] = q1 * r_q * gl[t+256];
    float res = kv * (isk ? r_k : r_v) * gkv[t & 127];
    if (isk) g_ka[(size_t)row*KVD_ + t]         = res;
    else     g_va[(size_t)row*KVD_ + (t - 128)] = res;
}

// ---------------- pre-out RMS -> packed hi/lo for final GEMM -----------------
__global__ __launch_bounds__(128) void rms_att_pack_kernel(const float* __restrict__ g)
{
    const int row = blockIdx.x, t = threadIdx.x;
    const float* ip = g_att + (size_t)row * LAT_;
    float4 v = *(const float4*)(ip + 4*t);
    float ss = v.x*v.x + v.y*v.y + v.z*v.z + v.w*v.w;
    ss = warpSum(ss);
    __shared__ float red[4];
    int lane = t & 31, wid = t >> 5;
    if (lane == 0) red[wid] = ss;
    __syncthreads();
    float r = rsqrtf((red[0]+red[1]+red[2]+red[3]) * (1.f/512.f) + EPS_);
    float4 gg = *(const float4*)(g + 4*t);
    float a0 = v.x*r*gg.x, a1 = v.y*r*gg.y, a2 = v.z*r*gg.z, a3 = v.w*r*gg.w;
    uint32_t lo0, lo1;
    uint32_t hi0 = pack2(a0, a1, lo0);
    uint32_t hi1 = pack2(a2, a3, lo1);
    size_t base = (size_t)row * (LAT_/2) + 2*t;
    g_ah[base] = hi0; g_ah[base+1] = hi1;
    g_al[base] = lo0; g_al[base+1] = lo1;
}

// ---------------- grouped causal conv (q: 512 ch, 16 groups) + RMS ----------
__global__ __launch_bounds__(256) void convq_kernel(
    const float* __restrict__ w, const float* __restrict__ g)
{
    const float* qin = g_qa; float* out = g_qb;
    const int row = blockIdx.x;
    const int s = row & (S_LEN - 1);
    __shared__ __align__(16) float xin[3][LAT_];
    __shared__ float red[8];
    const int t = threadIdx.x;
    #pragma unroll
    for (int tt = 0; tt < 3; tt++){
        int sr = s - 2 + tt;
        for (int i = t; i < LAT_; i += 256)
            xin[tt][i] = (sr >= 0) ? qin[(size_t)(row - 2 + tt) * LAT_ + i] : 0.f;
    }
    __syncthreads();
    float acc[2]; float ss = 0.f;
    #pragma unroll
    for (int cc = 0; cc < 2; cc++){
        int c = t + cc * 256;
        int grp = c >> 5;
        const float* wc = w + c * 96;
        const float* x0 = &xin[0][grp*32];
        const float* x1 = &xin[1][grp*32];
        const float* x2 = &xin[2][grp*32];
        float a = 0.f;
        #pragma unroll
        for (int i = 0; i < 32; i++)
            a += wc[i*3]*x0[i] + wc[i*3+1]*x1[i] + wc[i*3+2]*x2[i];
        acc[cc] = a; ss += a*a;
    }
    ss = warpSum(ss);
    int lane = t & 31, wid = t >> 5;
    if (lane == 0) red[wid] = ss;
    __syncthreads();
    float tot = 0.f;
    #pragma unroll
    for (int i = 0; i < 8; i++) tot += red[i];
    float r = rsqrtf(tot * (1.f/(float)LAT_) + EPS_);
    out[(size_t)row*LAT_ + t]       = acc[0] * r * g[t];
    out[(size_t)row*LAT_ + t + 256] = acc[1] * r * g[t+256];
}

// ---------------- grouped causal conv (k: 128 ch, 4 groups) + RMS -----------
__global__ __launch_bounds__(128) void convk_kernel(
    const float* __restrict__ w, const float* __restrict__ g)
{
    const float* kin = g_ka; float* out = g_kb;
    const int row = blockIdx.x;
    const int s = row & (S_LEN - 1);
    __shared__ __align__(16) float xin[3][KVD_];
    __shared__ float red[4];
    const int t = threadIdx.x;
    #pragma unroll
    for (int tt = 0; tt < 3; tt++){
        int sr = s - 2 + tt;
        xin[tt][t] = (sr >= 0) ? kin[(size_t)(row - 2 + tt) * KVD_ + t] : 0.f;
    }
    __syncthreads();
    int grp = t >> 5;
    const float* wc = w + t * 96;
    float a = 0.f;
    #pragma unroll
    for (int i = 0; i < 32; i++)
        a += wc[i*3]*xin[0][grp*32+i] + wc[i*3+1]*xin[1][grp*32+i] + wc[i*3+2]*xin[2][grp*32+i];
    float ss = warpSum(a*a);
    int lane = t & 31, wid = t >> 5;
    if (lane == 0) red[wid] = ss;
    __syncthreads();
    float r = rsqrtf((red[0]+red[1]+red[2]+red[3]) * (1.f/(float)KVD_) + EPS_);
    out[(size_t)row*KVD_ + t] = a * r * g[t];
}

// ---------------- post: means coupling, post-RMS, per-head norm, RoPE -------
__global__ __launch_bounds__(512) void post_kernel(
    const float* __restrict__ g_postq, const float* __restrict__ g_postk,
    const float* __restrict__ key_temp)
{
    const float* qpre = g_qa; const float* kpre = g_ka;
    float* qio = g_qb; float* kio = g_kb;
    const int row = blockIdx.x;
    const int s = row & (S_LEN - 1);
    const int t = threadIdx.x;
    const int lane = t & 31, wid = t >> 5;
    __shared__ float shq[LAT_];
    __shared__ float kmean[HD_], qmean[HD_];
    __shared__ float red[16];

    shq[t] = qpre[(size_t)row*LAT_ + t];
    __syncthreads();
    if (t < 32){
        float qm = 0.f;
        #pragma unroll
        for (int h = 0; h < NH_; h++) qm += shq[h*32 + t];
        qmean[t] = qm * (1.f/(float)NH_);
        float km = 0.f;
        #pragma unroll
        for (int kh = 0; kh < NKV_; kh++) km += kpre[(size_t)row*KVD_ + kh*32 + t];
        kmean[t] = km * (1.f/(float)NKV_);
    }
    __syncthreads();

    // RoPE from precomputed table
    const int j = lane >> 1;
    const float c  = g_ropec[s*16 + j];
    const float si = g_ropes[s*16 + j];

    // ---- Q path ----
    float qv = qio[(size_t)row*LAT_ + t] + GAIN_ * kmean[lane];
    float ss = warpSum(qv*qv);
    if (lane == 0) red[wid] = ss;
    __syncthreads();
    float tot = 0.f;
    #pragma unroll
    for (int i = 0; i < 16; i++) tot += red[i];
    float r = rsqrtf(tot * (1.f/(float)LAT_) + EPS_);
    qv = qv * r * g_postq[t];
    float n2 = warpSum(qv*qv);
    float nrm = fmaxf(sqrtf(n2), 1e-12f);
    qv = qv * (SQRT_HD / nrm);
    {
        float other = __shfl_xor_sync(0xffffffffu, qv, 1);
        float res = (lane & 1) ? fmaf(other, si, qv * c)
                               : fmaf(qv, c, -other * si);
        qio[(size_t)row*LAT_ + t] = res;
    }

    // ---- K path ----
    float kvv = (t < KVD_) ? (kio[(size_t)row*KVD_ + t] + GAIN_ * qmean[lane]) : 0.f;
    __syncthreads();
    float ssk = warpSum(kvv*kvv);
    if (lane == 0) red[wid] = ssk;
    __syncthreads();
    float totk = 0.f;
    #pragma unroll
    for (int i = 0; i < 16; i++) totk += red[i];
    if (t < KVD_){
        float rk = rsqrtf(totk * (1.f/(float)KVD_) + EPS_);
        kvv = kvv * rk * g_postk[t];
        float n2k = warpSum(kvv*kvv);
        float nk = fmaxf(sqrtf(n2k), 1e-12f);
        kvv = kvv * (SQRT_HD / nk) * key_temp[0];
        float other = __shfl_xor_sync(0xffffffffu, kvv, 1);
        float res = (lane & 1) ? fmaf(other, si, kvv * c)
                               : fmaf(kvv, c, -other * si);
        kio[(size_t)row*KVD_ + t] = res;
    }
}

// ------ flash attention, UNNORMALIZED softmax (bounded logits, no max) ------
// |logit| <= sqrt(32)*key_temp*~1 => exp safe in fp32; sum <= ~6e5.
__global__ __launch_bounds__(256) void flash_kernel()
{
    const float* Q = g_qb; const float* Kk = g_kb;
    const float* V = g_va; float* O = g_att;
    const int qt = blockIdx.x, h = blockIdx.y, b = blockIdx.z;
    const int kh = h >> 2;
    const int tid = threadIdx.x;
    const int tx = tid & 15, ty = tid >> 4;
    __shared__ __align__(16) float qs[64][36];
    __shared__ __align__(16) float ks[64][36];
    __shared__ __align__(16) float vs[64][36];
    __shared__ __align__(16) float ps[64][68];
    const int q0 = qt * 64;

    for (int idx = tid; idx < 512; idx += 256){
        int r = idx >> 3, cv = (idx & 7) * 4;
        *(float4*)&qs[r][cv] =
            *(const float4*)&Q[((size_t)(b*S_LEN + q0 + r))*LAT_ + h*HD_ + cv];
    }
    float l[4], o0[4], o1[4];
    #pragma unroll
    for (int r = 0; r < 4; r++){ l[r] = 0.f; o0[r] = 0.f; o1[r] = 0.f; }
    const float scale = 0.1767766952966369f; // 1/sqrt(32)
    const int d0 = tx * 2;

    for (int kt = 0; kt <= qt; kt++){
        const int k0 = kt * 64;
        __syncthreads();
        for (int idx = tid; idx < 512; idx += 256){
            int r = idx >> 3, cv = (idx & 7) * 4;
            size_t base = ((size_t)(b*S_LEN + k0 + r))*KVD_ + kh*HD_ + cv;
            *(float4*)&ks[r][cv] = *(const float4*)&Kk[base];
            *(float4*)&vs[r][cv] = *(const float4*)&V[base];
        }
        __syncthreads();

        float sc[4][4];
        #pragma unroll
        for (int r = 0; r < 4; r++)
            #pragma unroll
            for (int c = 0; c < 4; c++) sc[r][c] = 0.f;
        #pragma unroll
        for (int d = 0; d < 32; d += 4){
            float4 qa4[4], kb4[4];
            #pragma unroll
            for (int r = 0; r < 4; r++) qa4[r] = *(const float4*)&qs[ty*4+r][d];
            #pragma unroll
            for (int c = 0; c < 4; c++) kb4[c] = *(const float4*)&ks[tx*4+c][d];
            #pragma unroll
            for (int r = 0; r < 4; r++)
                #pragma unroll
                for (int c = 0; c < 4; c++){
                    sc[r][c] = fmaf(qa4[r].x, kb4[c].x, sc[r][c]);
                    sc[r][c] = fmaf(qa4[r].y, kb4[c].y, sc[r][c]);
                    sc[r][c] = fmaf(qa4[r].z, kb4[c].z, sc[r][c]);
                    sc[r][c] = fmaf(qa4[r].w, kb4[c].w, sc[r][c]);
                }
        }
        // exp (with causal mask on diagonal tile), accumulate partial row sums
        if (kt == qt){
            #pragma unroll
            for (int r = 0; r < 4; r++)
                #pragma unroll
                for (int c = 0; c < 4; c++){
                    bool ok = (k0 + tx*4 + c <= q0 + ty*4 + r);
                    float p = ok ? __expf(sc[r][c]*scale) : 0.f;
                    ps[ty*4+r][tx*4+c] = p;
                    l[r] += p;
                }
        } else {
            #pragma unroll
            for (int r = 0; r < 4; r++)
                #pragma unroll
                for (int c = 0; c < 4; c++){
                    float p = __expf(sc[r][c]*scale);
                    ps[ty*4+r][tx*4+c] = p;
                    l[r] += p;
                }
        }
        __syncthreads();
        #pragma unroll 4
        for (int n = 0; n < 64; n += 4){
            float4 p4[4];
            #pragma unroll
            for (int r = 0; r < 4; r++) p4[r] = *(const float4*)&ps[ty*4+r][n];
            #pragma unroll
            for (int jj = 0; jj < 4; jj++){
                float v0 = vs[n+jj][d0], v1 = vs[n+jj][d0+1];
                float p0 = (jj==0)?p4[0].x:(jj==1)?p4[0].y:(jj==2)?p4[0].z:p4[0].w;
                float p1 = (jj==0)?p4[1].x:(jj==1)?p4[1].y:(jj==2)?p4[1].z:p4[1].w;
                float p2 = (jj==0)?p4[2].x:(jj==1)?p4[2].y:(jj==2)?p4[2].z:p4[2].w;
                float p3 = (jj==0)?p4[3].x:(jj==1)?p4[3].y:(jj==2)?p4[3].z:p4[3].w;
                o0[0] = fmaf(p0, v0, o0[0]); o1[0] = fmaf(p0, v1, o1[0]);
                o0[1] = fmaf(p1, v0, o0[1]); o1[1] = fmaf(p1, v1, o1[1]);
                o0[2] = fmaf(p2, v0, o0[2]); o1[2] = fmaf(p2, v1, o1[2]);
                o0[3] = fmaf(p3, v0, o0[3]); o1[3] = fmaf(p3, v1, o1[3]);
            }
        }
    }
    // one final reduction of row sums across the 16 tx threads
    #pragma unroll
    for (int r = 0; r < 4; r++){
        float lr = l[r];
        #pragma unroll
        for (int off = 8; off; off >>= 1)
            lr += __shfl_xor_sync(0xffffffffu, lr, off, 16);
        float inv = 1.f / lr;
        size_t base = ((size_t)(b*S_LEN + q0 + ty*4 + r))*LAT_ + h*HD_ + d0;
        O[base]   = o0[r] * inv;
        O[base+1] = o1[r] * inv;
    }
}

// ---------------- host launcher ---------------------------------------------
extern "C" void kernel_launch(void* const* d_in, const int* in_sizes, int n_in,
                              void* d_out, int out_size)
{
    const float *x, *w_q, *w_k, *w_v, *g_latent, *g_kv, *conv_q_w, *conv_k_w;
    const float *g_conv, *g_kconv, *g_postq, *g_postk, *key_temp, *g_preout, *w_o;

    if (n_in >= 15 && in_sizes[0] == M_ROWS * DIM_) {
        x        = (const float*)d_in[0];
        w_q      = (const float*)d_in[1];
        w_k      = (const float*)d_in[2];
        w_v      = (const float*)d_in[3];
        g_latent = (const float*)d_in[4];
        g_kv     = (const float*)d_in[5];
        conv_q_w = (const float*)d_in[6];
        conv_k_w = (const float*)d_in[7];
        g_conv   = (const float*)d_in[8];
        g_kconv  = (const float*)d_in[9];
        g_postq  = (const float*)d_in[10];
        g_postk  = (const float*)d_in[11];
        key_temp = (const float*)d_in[12];
        g_preout = (const float*)d_in[13];
        w_o      = (const float*)d_in[14];
    } else {
        conv_k_w = (const float*)d_in[0];
        conv_q_w = (const float*)d_in[1];
        g_conv   = (const float*)d_in[2];
        g_kconv  = (const float*)d_in[3];
        g_kv     = (const float*)d_in[4];
        g_latent = (const float*)d_in[5];
        g_postk  = (const float*)d_in[6];
        g_postq  = (const float*)d_in[7];
        g_preout = (const float*)d_in[8];
        key_temp = (const float*)d_in[9];
        w_k      = (const float*)d_in[10];
        w_o      = (const float*)d_in[11];
        w_q      = (const float*)d_in[12];
        w_v      = (const float*)d_in[13];
        x        = (const float*)d_in[14];
    }
    float* out = (float*)d_out;

    rope_table_kernel<<<S_LEN, 16>>>();
    pack_x_kernel<<<(M_ROWS*(DIM_/2)+255)/256, 256>>>(x);
    wpack_kernel<<<(LAT_*(DIM_/2)+255)/256, 256>>>(w_q, 0);
    wpack_kernel<<<(KVD_*(DIM_/2)+255)/256, 256>>>(w_k, 1);
    wpack_kernel<<<(KVD_*(DIM_/2)+255)/256, 256>>>(w_v, 2);
    wpack_kernel<<<(DIM_*(LAT_/2)+255)/256, 256>>>(w_o, 3);

    gemm_fp16x2_kernel<<<dim3(QKV_N/GBN, M_ROWS/GBM), 512>>>(nullptr, 0);

    rms_qkv_kernel<<<M_ROWS, 256>>>(g_latent, g_kv);

    convq_kernel<<<M_ROWS, 256>>>(conv_q_w, g_conv);
    convk_kernel<<<M_ROWS, 128>>>(conv_k_w, g_kconv);

    post_kernel<<<M_ROWS, 512>>>(g_postq, g_postk, key_temp);

    flash_kernel<<<dim3(S_LEN/64, NH_, B_SZ), 256>>>();

    rms_att_pack_kernel<<<M_ROWS, 128>>>(g_preout);

    gemm_fp16x2_kernel<<<dim3(DIM_/GBN, M_ROWS/GBM), 512>>>(out, 1);
}

// round 16
// speedup vs baseline: 1.0049x; 1.0042x over previous
#include <cuda_runtime.h>
#include <cuda_bf16.h>
#include <cuda_fp16.h>
#include <cstdint>
#include <math.h>

#define S_LEN 2048
#define B_SZ  4
#define M_ROWS (B_SZ*S_LEN)      // 8192
#define DIM_  2048
#define LAT_  512
#define KVD_  128
#define QKV_N 768                // 512 q | 128 k | 128 v
#define NH_   16
#define NKV_  4
#define HD_   32
#define EPS_  1e-6f
#define GAIN_ 0.25f
#define SQRT_HD 5.656854249492381f

// ---------------- scratch (device globals; no runtime allocation) ----------
__device__ uint32_t g_xh    [M_ROWS*(DIM_/2)];   // x packed fp16 hi pairs
__device__ uint32_t g_xl    [M_ROWS*(DIM_/2)];   // x packed fp16 lo pairs
__device__ uint32_t g_wqkvTh[(DIM_/2)*QKV_N];    // W^T qkv packed hi
__device__ uint32_t g_wqkvTl[(DIM_/2)*QKV_N];
__device__ uint32_t g_woTh  [(LAT_/2)*DIM_];     // W_o^T packed hi
__device__ uint32_t g_woTl  [(LAT_/2)*DIM_];
__device__ uint32_t g_ah    [M_ROWS*(LAT_/2)];   // rms(att) packed hi
__device__ uint32_t g_al    [M_ROWS*(LAT_/2)];
__device__ float g_qkv[M_ROWS*QKV_N];   // raw fused qkv gemm output
__device__ float g_qa  [M_ROWS*LAT_];   // q_pre (after rms g_latent)
__device__ float g_ka  [M_ROWS*KVD_];   // k_pre
__device__ float g_va  [M_ROWS*KVD_];   // v final
__device__ float g_qb  [M_ROWS*LAT_];   // conv out -> final q
__device__ float g_kb  [M_ROWS*KVD_];   // conv out -> final k
__device__ float g_att [M_ROWS*LAT_];   // attention output
__device__ float g_ropec[S_LEN*16];     // RoPE cos table (s, j)
__device__ float g_ropes[S_LEN*16];     // RoPE sin table (s, j)

__device__ __forceinline__ float warpSum(float v){
    #pragma unroll
    for (int o = 16; o; o >>= 1) v += __shfl_xor_sync(0xffffffffu, v, o);
    return v;
}

// split (a,b) into fp16 hi pair (returned) and lo pair (out param)
__device__ __forceinline__ uint32_t pack2(float a, float b, uint32_t& lo){
    __half ha = __float2half_rn(a), hb = __float2half_rn(b);
    __half la = __float2half_rn(a - __half2float(ha));
    __half lb = __float2half_rn(b - __half2float(hb));
    lo = (uint32_t)__half_as_ushort(la) | ((uint32_t)__half_as_ushort(lb) << 16);
    return (uint32_t)__half_as_ushort(ha) | ((uint32_t)__half_as_ushort(hb) << 16);
}

#define MMA_F16(c, a0,a1,a2,a3, b0,b1) \
  asm volatile("mma.sync.aligned.m16n8k16.row.col.f32.f16.f16.f32 " \
    "{%0,%1,%2,%3}, {%4,%5,%6,%7}, {%8,%9}, {%0,%1,%2,%3};" \
    : "+f"((c)[0]),"+f"((c)[1]),"+f"((c)[2]),"+f"((c)[3]) \
    : "r"(a0),"r"(a1),"r"(a2),"r"(a3),"r"(b0),"r"(b1))

// ---------------- RoPE table (one-time tiny kernel, fp64 off hot path) ------
__global__ void rope_table_kernel(){
    int s = blockIdx.x, j = threadIdx.x;            // j in [0,16)
    float freq = 1.0f / powf(10000.f, (float)(2*j) * (1.f/(float)HD_));
    float fang = (float)s * freq;                    // fp32 (matches jax)
    double sd_, cd_; sincos((double)fang, &sd_, &cd_);
    g_ropec[s*16 + j] = (float)cd_;
    g_ropes[s*16 + j] = (float)sd_;
}

// ---------------- pack x into hi/lo fp16 pair arrays ------------------------
__global__ void pack_x_kernel(const float* __restrict__ x){
    int idx = blockIdx.x * blockDim.x + threadIdx.x;
    if (idx >= M_ROWS * (DIM_/2)) return;
    float2 v = ((const float2*)x)[idx];
    uint32_t lo, hi = pack2(v.x, v.y, lo);
    g_xh[idx] = hi; g_xl[idx] = lo;
}

// ---------------- weight transpose+pack (sel: 0 wq, 1 wk, 2 wv, 3 wo) -------
__global__ void wpack_kernel(const float* __restrict__ w, int sel){
    int N, K2, ldOut, colOff; uint32_t *oh, *ol;
    if      (sel == 0){ N = LAT_; K2 = DIM_/2; ldOut = QKV_N; colOff = 0;   oh = g_wqkvTh; ol = g_wqkvTl; }
    else if (sel == 1){ N = KVD_; K2 = DIM_/2; ldOut = QKV_N; colOff = 512; oh = g_wqkvTh; ol = g_wqkvTl; }
    else if (sel == 2){ N = KVD_; K2 = DIM_/2; ldOut = QKV_N; colOff = 640; oh = g_wqkvTh; ol = g_wqkvTl; }
    else              { N = DIM_; K2 = LAT_/2; ldOut = DIM_;  colOff = 0;   oh = g_woTh;   ol = g_woTl;   }
    int idx = blockIdx.x * blockDim.x + threadIdx.x;
    if (idx >= N * K2) return;
    int n = idx / K2, p = idx - n * K2;
    float2 v = ((const float2*)w)[idx];
    uint32_t lo, hi = pack2(v.x, v.y, lo);
    oh[(size_t)p * ldOut + colOff + n] = hi;
    ol[(size_t)p * ldOut + colOff + n] = lo;
}

// ------------ 3x-split fp16 tensor-core GEMM: C[MxN] = A[MxK]*B[KxN] --------
#define GBM 128
#define GBN 128
#define SPAD 136
__global__ __launch_bounds__(512) void gemm_fp16x2_kernel(float* __restrict__ Cext, int sel)
{
    const uint32_t *Ah, *Al, *Bh, *Bl; float* C; int N, K2;
    if (sel == 0){ Ah = g_xh; Al = g_xl; Bh = g_wqkvTh; Bl = g_wqkvTl; C = g_qkv; N = QKV_N; K2 = DIM_/2; }
    else         { Ah = g_ah; Al = g_al; Bh = g_woTh;   Bl = g_woTl;   C = Cext;  N = DIM_;  K2 = LAT_/2; }

    __shared__ uint32_t AsH[2][8][SPAD], AsL[2][8][SPAD];
    __shared__ uint32_t BsH[2][8][SPAD], BsL[2][8][SPAD];

    const int tid  = threadIdx.x;
    const int warp = tid >> 5, lane = tid & 31;
    const int g = lane >> 2, tig = lane & 3;
    const int m0 = (warp >> 2) * 32;
    const int n0 = (warp & 3) * 32;

    const int aM = tid >> 2, aP = (tid & 3) * 2;
    const int bP = tid >> 6, bN = (tid & 63) * 2;

    const uint32_t* ApH = Ah + (size_t)(blockIdx.y * GBM + aM) * K2 + aP;
    const uint32_t* ApL = Al + (size_t)(blockIdx.y * GBM + aM) * K2 + aP;
    const uint32_t* BpH = Bh + (size_t)bP * N + blockIdx.x * GBN + bN;
    const uint32_t* BpL = Bl + (size_t)bP * N + blockIdx.x * GBN + bN;

    float acc[2][4][4];
    #pragma unroll
    for (int mt = 0; mt < 2; mt++)
        #pragma unroll
        for (int nt = 0; nt < 4; nt++)
            #pragma unroll
            for (int i = 0; i < 4; i++) acc[mt][nt][i] = 0.f;

    const int stages = K2 / 8;
    uint2 pah = *(const uint2*)ApH; uint2 pal = *(const uint2*)ApL;
    uint2 pbh = *(const uint2*)BpH; uint2 pbl = *(const uint2*)BpL;
    AsH[0][aP][aM] = pah.x; AsH[0][aP+1][aM] = pah.y;
    AsL[0][aP][aM] = pal.x; AsL[0][aP+1][aM] = pal.y;
    BsH[0][bP][bN] = pbh.x; BsH[0][bP][bN+1] = pbh.y;
    BsL[0][bP][bN] = pbl.x; BsL[0][bP][bN+1] = pbl.y;
    __syncthreads();

    for (int s = 0; s < stages; s++){
        const int cur = s & 1;
        if (s + 1 < stages){
            pah = *(const uint2*)(ApH + (s+1)*8);
            pal = *(const uint2*)(ApL + (s+1)*8);
            pbh = *(const uint2*)(BpH + (size_t)(s+1)*8 * N);
            pbl = *(const uint2*)(BpL + (size_t)(s+1)*8 * N);
        }
        uint32_t bh[4][2], bl[4][2];
        #pragma unroll
        for (int nt = 0; nt < 4; nt++){
            bh[nt][0] = BsH[cur][tig  ][n0 + nt*8 + g];
            bh[nt][1] = BsH[cur][tig+4][n0 + nt*8 + g];
            bl[nt][0] = BsL[cur][tig  ][n0 + nt*8 + g];
            bl[nt][1] = BsL[cur][tig+4][n0 + nt*8 + g];
        }
        #pragma unroll
        for (int mt = 0; mt < 2; mt++){
            uint32_t ah0 = AsH[cur][tig  ][m0 + mt*16 + g    ];
            uint32_t ah1 = AsH[cur][tig  ][m0 + mt*16 + g + 8];
            uint32_t ah2 = AsH[cur][tig+4][m0 + mt*16 + g    ];
            uint32_t ah3 = AsH[cur][tig+4][m0 + mt*16 + g + 8];
            uint32_t al0 = AsL[cur][tig  ][m0 + mt*16 + g    ];
            uint32_t al1 = AsL[cur][tig  ][m0 + mt*16 + g + 8];
            uint32_t al2 = AsL[cur][tig+4][m0 + mt*16 + g    ];
            uint32_t al3 = AsL[cur][tig+4][m0 + mt*16 + g + 8];
            #pragma unroll
            for (int nt = 0; nt < 4; nt++){
                MMA_F16(acc[mt][nt], ah0,ah1,ah2,ah3, bh[nt][0], bh[nt][1]);
                MMA_F16(acc[mt][nt], ah0,ah1,ah2,ah3, bl[nt][0], bl[nt][1]);
                MMA_F16(acc[mt][nt], al0,al1,al2,al3, bh[nt][0], bh[nt][1]);
            }
        }
        if (s + 1 < stages){
            const int nxt = cur ^ 1;
            AsH[nxt][aP][aM] = pah.x; AsH[nxt][aP+1][aM] = pah.y;
            AsL[nxt][aP][aM] = pal.x; AsL[nxt][aP+1][aM] = pal.y;
            BsH[nxt][bP][bN] = pbh.x; BsH[nxt][bP][bN+1] = pbh.y;
            BsL[nxt][bP][bN] = pbl.x; BsL[nxt][bP][bN+1] = pbl.y;
        }
        __syncthreads();
    }

    const int rowBase = blockIdx.y * GBM + m0 + g;
    const int colBase = blockIdx.x * GBN + n0;
    #pragma unroll
    for (int mt = 0; mt < 2; mt++){
        #pragma unroll
        for (int nt = 0; nt < 4; nt++){
            int row = rowBase + mt*16;
            int col = colBase + nt*8 + tig*2;
            *(float2*)&C[(size_t)row * N + col]       = make_float2(acc[mt][nt][0], acc[mt][nt][1]);
            *(float2*)&C[(size_t)(row + 8) * N + col] = make_float2(acc[mt][nt][2], acc[mt][nt][3]);
        }
    }
}

// ---------------- fused RMS over packed qkv output ---------------------------
__global__ __launch_bounds__(256) void rms_qkv_kernel(
    const float* __restrict__ gl, const float* __restrict__ gkv)
{
    const int row = blockIdx.x, t = threadIdx.x;
    const float* ip = g_qkv + (size_t)row * QKV_N;
    float q0 = ip[t], q1 = ip[t+256], kv = ip[512+t];
    bool isk = t < 128;
    float ssq = q0*q0 + q1*q1;
    float skv = kv*kv;
    float sk = isk ? skv : 0.f, sv = isk ? 0.f : skv;
    ssq = warpSum(ssq); sk = warpSum(sk); sv = warpSum(sv);
    __shared__ float rq[8], rk[8], rv[8];
    int lane = t & 31, wid = t >> 5;
    if (lane == 0){ rq[wid] = ssq; rk[wid] = sk; rv[wid] = sv; }
    __syncthreads();
    float tq = 0.f, tk = 0.f, tv = 0.f;
    #pragma unroll
    for (int i = 0; i < 8; i++){ tq += rq[i]; tk += rk[i]; tv += rv[i]; }
    float r_q = rsqrtf(tq * (1.f/512.f) + EPS_);
    float r_k = rsqrtf(tk * (1.f/128.f) + EPS_);
    float r_v = rsqrtf(tv * (1.f/128.f) + EPS_);
    g_qa[(size_t)row*LAT_ + t]       = q0 * r_q * gl[t];
    g_qa[(size_t)row*LAT_ + t + 256] = q1 * r_q * gl[t+256];
    float res = kv * (isk ? r_k : r_v) * gkv[t & 127];
    if (isk) g_ka[(size_t)row*KVD_ + t]         = res;
    else     g_va[(size_t)row*KVD_ + (t - 128)] = res;
}

// ---------------- pre-out RMS -> packed hi/lo for final GEMM -----------------
__global__ __launch_bounds__(128) void rms_att_pack_kernel(const float* __restrict__ g)
{
    const int row = blockIdx.x, t = threadIdx.x;
    const float* ip = g_att + (size_t)row * LAT_;
    float4 v = *(const float4*)(ip + 4*t);
    float ss = v.x*v.x + v.y*v.y + v.z*v.z + v.w*v.w;
    ss = warpSum(ss);
    __shared__ float red[4];
    int lane = t & 31, wid = t >> 5;
    if (lane == 0) red[wid] = ss;
    __syncthreads();
    float r = rsqrtf((red[0]+red[1]+red[2]+red[3]) * (1.f/512.f) + EPS_);
    float4 gg = *(const float4*)(g + 4*t);
    float a0 = v.x*r*gg.x, a1 = v.y*r*gg.y, a2 = v.z*r*gg.z, a3 = v.w*r*gg.w;
    uint32_t lo0, lo1;
    uint32_t hi0 = pack2(a0, a1, lo0);
    uint32_t hi1 = pack2(a2, a3, lo1);
    size_t base = (size_t)row * (LAT_/2) + 2*t;
    g_ah[base] = hi0; g_ah[base+1] = hi1;
    g_al[base] = lo0; g_al[base+1] = lo1;
}

// ---------------- grouped causal conv (q: 512 ch, 16 groups) + RMS ----------
__global__ __launch_bounds__(256) void convq_kernel(
    const float* __restrict__ w, const float* __restrict__ g)
{
    const float* qin = g_qa; float* out = g_qb;
    const int row = blockIdx.x;
    const int s = row & (S_LEN - 1);
    __shared__ __align__(16) float xin[3][LAT_];
    __shared__ float red[8];
    const int t = threadIdx.x;
    #pragma unroll
    for (int tt = 0; tt < 3; tt++){
        int sr = s - 2 + tt;
        for (int i = t; i < LAT_; i += 256)
            xin[tt][i] = (sr >= 0) ? qin[(size_t)(row - 2 + tt) * LAT_ + i] : 0.f;
    }
    __syncthreads();
    float acc[2]; float ss = 0.f;
    #pragma unroll
    for (int cc = 0; cc < 2; cc++){
        int c = t + cc * 256;
        int grp = c >> 5;
        const float* wc = w + c * 96;
        const float* x0 = &xin[0][grp*32];
        const float* x1 = &xin[1][grp*32];
        const float* x2 = &xin[2][grp*32];
        float a = 0.f;
        #pragma unroll
        for (int i = 0; i < 32; i++)
            a += wc[i*3]*x0[i] + wc[i*3+1]*x1[i] + wc[i*3+2]*x2[i];
        acc[cc] = a; ss += a*a;
    }
    ss = warpSum(ss);
    int lane = t & 31, wid = t >> 5;
    if (lane == 0) red[wid] = ss;
    __syncthreads();
    float tot = 0.f;
    #pragma unroll
    for (int i = 0; i < 8; i++) tot += red[i];
    float r = rsqrtf(tot * (1.f/(float)LAT_) + EPS_);
    out[(size_t)row*LAT_ + t]       = acc[0] * r * g[t];
    out[(size_t)row*LAT_ + t + 256] = acc[1] * r * g[t+256];
}

// ---------------- grouped causal conv (k: 128 ch, 4 groups) + RMS -----------
__global__ __launch_bounds__(128) void convk_kernel(
    const float* __restrict__ w, const float* __restrict__ g)
{
    const float* kin = g_ka; float* out = g_kb;
    const int row = blockIdx.x;
    const int s = row & (S_LEN - 1);
    __shared__ __align__(16) float xin[3][KVD_];
    __shared__ float red[4];
    const int t = threadIdx.x;
    #pragma unroll
    for (int tt = 0; tt < 3; tt++){
        int sr = s - 2 + tt;
        xin[tt][t] = (sr >= 0) ? kin[(size_t)(row - 2 + tt) * KVD_ + t] : 0.f;
    }
    __syncthreads();
    int grp = t >> 5;
    const float* wc = w + t * 96;
    float a = 0.f;
    #pragma unroll
    for (int i = 0; i < 32; i++)
        a += wc[i*3]*xin[0][grp*32+i] + wc[i*3+1]*xin[1][grp*32+i] + wc[i*3+2]*xin[2][grp*32+i];
    float ss = warpSum(a*a);
    int lane = t & 31, wid = t >> 5;
    if (lane == 0) red[wid] = ss;
    __syncthreads();
    float r = rsqrtf((red[0]+red[1]+red[2]+red[3]) * (1.f/(float)KVD_) + EPS_);
    out[(size_t)row*KVD_ + t] = a * r * g[t];
}

// ---------------- post: means coupling, post-RMS, per-head norm, RoPE -------
__global__ __launch_bounds__(512) void post_kernel(
    const float* __restrict__ g_postq, const float* __restrict__ g_postk,
    const float* __restrict__ key_temp)
{
    const float* qpre = g_qa; const float* kpre = g_ka;
    float* qio = g_qb; float* kio = g_kb;
    const int row = blockIdx.x;
    const int s = row & (S_LEN - 1);
    const int t = threadIdx.x;
    const int lane = t & 31, wid = t >> 5;
    __shared__ float shq[LAT_];
    __shared__ float kmean[HD_], qmean[HD_];
    __shared__ float red[16];

    shq[t] = qpre[(size_t)row*LAT_ + t];
    __syncthreads();
    if (t < 32){
        float qm = 0.f;
        #pragma unroll
        for (int h = 0; h < NH_; h++) qm += shq[h*32 + t];
        qmean[t] = qm * (1.f/(float)NH_);
        float km = 0.f;
        #pragma unroll
        for (int kh = 0; kh < NKV_; kh++) km += kpre[(size_t)row*KVD_ + kh*32 + t];
        kmean[t] = km * (1.f/(float)NKV_);
    }
    __syncthreads();

    // RoPE from precomputed table
    const int j = lane >> 1;
    const float c  = g_ropec[s*16 + j];
    const float si = g_ropes[s*16 + j];

    // ---- Q path ----
    float qv = qio[(size_t)row*LAT_ + t] + GAIN_ * kmean[lane];
    float ss = warpSum(qv*qv);
    if (lane == 0) red[wid] = ss;
    __syncthreads();
    float tot = 0.f;
    #pragma unroll
    for (int i = 0; i < 16; i++) tot += red[i];
    float r = rsqrtf(tot * (1.f/(float)LAT_) + EPS_);
    qv = qv * r * g_postq[t];
    float n2 = warpSum(qv*qv);
    float nrm = fmaxf(sqrtf(n2), 1e-12f);
    qv = qv * (SQRT_HD / nrm);
    {
        float other = __shfl_xor_sync(0xffffffffu, qv, 1);
        float res = (lane & 1) ? fmaf(other, si, qv * c)
                               : fmaf(qv, c, -other * si);
        qio[(size_t)row*LAT_ + t] = res;
    }

    // ---- K path ----
    float kvv = (t < KVD_) ? (kio[(size_t)row*KVD_ + t] + GAIN_ * qmean[lane]) : 0.f;
    __syncthreads();
    float ssk = warpSum(kvv*kvv);
    if (lane == 0) red[wid] = ssk;
    __syncthreads();
    float totk = 0.f;
    #pragma unroll
    for (int i = 0; i < 16; i++) totk += red[i];
    if (t < KVD_){
        float rk = rsqrtf(totk * (1.f/(float)KVD_) + EPS_);
        kvv = kvv * rk * g_postk[t];
        float n2k = warpSum(kvv*kvv);
        float nk = fmaxf(sqrtf(n2k), 1e-12f);
        kvv = kvv * (SQRT_HD / nk) * key_temp[0];
        float other = __shfl_xor_sync(0xffffffffu, kvv, 1);
        float res = (lane & 1) ? fmaf(other, si, kvv * c)
                               : fmaf(kvv, c, -other * si);
        kio[(size_t)row*KVD_ + t] = res;
    }
}

// ------ flash attention, UNNORMALIZED softmax (bounded logits, no max) ------
// |logit| <= sqrt(32)*key_temp*~1 => exp safe in fp32; sum <= ~6e5.
__global__ __launch_bounds__(256) void flash_kernel()
{
    const float* Q = g_qb; const float* Kk = g_kb;
    const float* V = g_va; float* O = g_att;
    const int qt = blockIdx.x, h = blockIdx.y, b = blockIdx.z;
    const int kh = h >> 2;
    const int tid = threadIdx.x;
    const int tx = tid & 15, ty = tid >> 4;
    __shared__ __align__(16) float qs[64][36];
    __shared__ __align__(16) float ks[64][36];
    __shared__ __align__(16) float vs[64][36];
    __shared__ __align__(16) float ps[64][68];
    const int q0 = qt * 64;

    for (int idx = tid; idx < 512; idx += 256){
        int r = idx >> 3, cv = (idx & 7) * 4;
        *(float4*)&qs[r][cv] =
            *(const float4*)&Q[((size_t)(b*S_LEN + q0 + r))*LAT_ + h*HD_ + cv];
    }
    float l[4], o0[4], o1[4];
    #pragma unroll
    for (int r = 0; r < 4; r++){ l[r] = 0.f; o0[r] = 0.f; o1[r] = 0.f; }
    const float scale = 0.1767766952966369f; // 1/sqrt(32)
    const int d0 = tx * 2;

    for (int kt = 0; kt <= qt; kt++){
        const int k0 = kt * 64;
        __syncthreads();
        for (int idx = tid; idx < 512; idx += 256){
            int r = idx >> 3, cv = (idx & 7) * 4;
            size_t base = ((size_t)(b*S_LEN + k0 + r))*KVD_ + kh*HD_ + cv;
            *(float4*)&ks[r][cv] = *(const float4*)&Kk[base];
            *(float4*)&vs[r][cv] = *(const float4*)&V[base];
        }
        __syncthreads();

        float sc[4][4];
        #pragma unroll
        for (int r = 0; r < 4; r++)
            #pragma unroll
            for (int c = 0; c < 4; c++) sc[r][c] = 0.f;
        #pragma unroll
        for (int d = 0; d < 32; d += 4){
            float4 qa4[4], kb4[4];
            #pragma unroll
            for (int r = 0; r < 4; r++) qa4[r] = *(const float4*)&qs[ty*4+r][d];
            #pragma unroll
            for (int c = 0; c < 4; c++) kb4[c] = *(const float4*)&ks[tx*4+c][d];
            #pragma unroll
            for (int r = 0; r < 4; r++)
                #pragma unroll
                for (int c = 0; c < 4; c++){
                    sc[r][c] = fmaf(qa4[r].x, kb4[c].x, sc[r][c]);
                    sc[r][c] = fmaf(qa4[r].y, kb4[c].y, sc[r][c]);
                    sc[r][c] = fmaf(qa4[r].z, kb4[c].z, sc[r][c]);
                    sc[r][c] = fmaf(qa4[r].w, kb4[c].w, sc[r][c]);
                }
        }
        // exp (with causal mask on diagonal tile), accumulate partial row sums
        if (kt == qt){
            #pragma unroll
            for (int r = 0; r < 4; r++)
                #pragma unroll
                for (int c = 0; c < 4; c++){
                    bool ok = (k0 + tx*4 + c <= q0 + ty*4 + r);
                    float p = ok ? __expf(sc[r][c]*scale) : 0.f;
                    ps[ty*4+r][tx*4+c] = p;
                    l[r] += p;
                }
        } else {
            #pragma unroll
            for (int r = 0; r < 4; r++)
                #pragma unroll
                for (int c = 0; c < 4; c++){
                    float p = __expf(sc[r][c]*scale);
                    ps[ty*4+r][tx*4+c] = p;
                    l[r] += p;
                }
        }
        __syncthreads();
        #pragma unroll 4
        for (int n = 0; n < 64; n += 4){
            float4 p4[4];
            #pragma unroll
            for (int r = 0; r < 4; r++) p4[r] = *(const float4*)&ps[ty*4+r][n];
            #pragma unroll
            for (int jj = 0; jj < 4; jj++){
                float v0 = vs[n+jj][d0], v1 = vs[n+jj][d0+1];
                float p0 = (jj==0)?p4[0].x:(jj==1)?p4[0].y:(jj==2)?p4[0].z:p4[0].w;
                float p1 = (jj==0)?p4[1].x:(jj==1)?p4[1].y:(jj==2)?p4[1].z:p4[1].w;
                float p2 = (jj==0)?p4[2].x:(jj==1)?p4[2].y:(jj==2)?p4[2].z:p4[2].w;
                float p3 = (jj==0)?p4[3].x:(jj==1)?p4[3].y:(jj==2)?p4[3].z:p4[3].w;
                o0[0] = fmaf(p0, v0, o0[0]); o1[0] = fmaf(p0, v1, o1[0]);
                o0[1] = fmaf(p1, v0, o0[1]); o1[1] = fmaf(p1, v1, o1[1]);
                o0[2] = fmaf(p2, v0, o0[2]); o1[2] = fmaf(p2, v1, o1[2]);
                o0[3] = fmaf(p3, v0, o0[3]); o1[3] = fmaf(p3, v1, o1[3]);
            }
        }
    }
    // one final reduction of row sums across the 16 tx threads
    #pragma unroll
    for (int r = 0; r < 4; r++){
        float lr = l[r];
        #pragma unroll
        for (int off = 8; off; off >>= 1)
            lr += __shfl_xor_sync(0xffffffffu, lr, off, 16);
        float inv = 1.f / lr;
        size_t base = ((size_t)(b*S_LEN + q0 + ty*4 + r))*LAT_ + h*HD_ + d0;
        O[base]   = o0[r] * inv;
        O[base+1] = o1[r] * inv;
    }
}

// ---------------- host launcher ---------------------------------------------
extern "C" void kernel_launch(void* const* d_in, const int* in_sizes, int n_in,
                              void* d_out, int out_size)
{
    const float *x, *w_q, *w_k, *w_v, *g_latent, *g_kv, *conv_q_w, *conv_k_w;
    const float *g_conv, *g_kconv, *g_postq, *g_postk, *key_temp, *g_preout, *w_o;

    if (n_in >= 15 && in_sizes[0] == M_ROWS * DIM_) {
        x        = (const float*)d_in[0];
        w_q      = (const float*)d_in[1];
        w_k      = (const float*)d_in[2];
        w_v      = (const float*)d_in[3];
        g_latent = (const float*)d_in[4];
        g_kv     = (const float*)d_in[5];
        conv_q_w = (const float*)d_in[6];
        conv_k_w = (const float*)d_in[7];
        g_conv   = (const float*)d_in[8];
        g_kconv  = (const float*)d_in[9];
        g_postq  = (const float*)d_in[10];
        g_postk  = (const float*)d_in[11];
        key_temp = (const float*)d_in[12];
        g_preout = (const float*)d_in[13];
        w_o      = (const float*)d_in[14];
    } else {
        conv_k_w = (const float*)d_in[0];
        conv_q_w = (const float*)d_in[1];
        g_conv   = (const float*)d_in[2];
        g_kconv  = (const float*)d_in[3];
        g_kv     = (const float*)d_in[4];
        g_latent = (const float*)d_in[5];
        g_postk  = (const float*)d_in[6];
        g_postq  = (const float*)d_in[7];
        g_preout = (const float*)d_in[8];
        key_temp = (const float*)d_in[9];
        w_k      = (const float*)d_in[10];
        w_o      = (const float*)d_in[11];
        w_q      = (const float*)d_in[12];
        w_v      = (const float*)d_in[13];
        x        = (const float*)d_in[14];
    }
    float* out = (float*)d_out;

    rope_table_kernel<<<S_LEN, 16>>>();
    pack_x_kernel<<<(M_ROWS*(DIM_/2)+255)/256, 256>>>(x);
    wpack_kernel<<<(LAT_*(DIM_/2)+255)/256, 256>>>(w_q, 0);
    wpack_kernel<<<(KVD_*(DIM_/2)+255)/256, 256>>>(w_k, 1);
    wpack_kernel<<<(KVD_*(DIM_/2)+255)/256, 256>>>(w_v, 2);
    wpack_kernel<<<(DIM_*(LAT_/2)+255)/256, 256>>>(w_o, 3);

    gemm_fp16x2_kernel<<<dim3(QKV_N/GBN, M_ROWS/GBM), 512>>>(nullptr, 0);

    rms_qkv_kernel<<<M_ROWS, 256>>>(g_latent, g_kv);

    convq_kernel<<<M_ROWS, 256>>>(conv_q_w, g_conv);
    convk_kernel<<<M_ROWS, 128>>>(conv_k_w, g_kconv);

    post_kernel<<<M_ROWS, 512>>>(g_postq, g_postk, key_temp);

    flash_kernel<<<dim3(S_LEN/64, NH_, B_SZ), 256>>>();

    rms_att_pack_kernel<<<M_ROWS, 128>>>(g_preout);

    gemm_fp16x2_kernel<<<dim3(DIM_/GBN, M_ROWS/GBM), 512>>>(out, 1);
}